// round 4
// baseline (speedup 1.0000x reference)
#include <cuda_runtime.h>
#include <math.h>

#define MAXROWS 4096
typedef unsigned long long ull;

// Precomputed pair-group coefficients.
// g_A : float, layout [(g*4+p)*n + row]          (packed over i at load time)
// g_Bd: ull (value duplicated in both halves), layout [(g*4+p)*m + col]
__device__ float g_A[32 * MAXROWS];
__device__ ull   g_Bd[32 * MAXROWS];

// Packed f32x2 helpers (Blackwell sm_100+).
#define MUL_F32X2(out, a, b) \
    asm("mul.rn.f32x2 %0, %1, %2;" : "=l"(out) : "l"(a), "l"(b))
#define FMA_F32X2(acc, a, b) \
    asm("fma.rn.f32x2 %0, %1, %2, %0;" : "+l"(acc) : "l"(a), "l"(b))
#define ABS_F32X2(out, a) \
    asm("and.b64 %0, %1, %2;" : "=l"(out) : "l"(a), "l"(0x7FFFFFFF7FFFFFFFULL))
#define UNPACK_F32X2(lo, hi, v) \
    asm("mov.b64 {%0, %1}, %2;" : "=f"(lo), "=f"(hi) : "l"(v))
#define DUP_TO_ULL(out, v) \
    asm("mov.b64 %0, {%1, %1};" : "=l"(out) : "f"(v))

// ---------------------------------------------------------------------------
// Precompute per row r, wire-pair g: (c0*c1, c0*s1, s0*c1, s0*s1).
// x rows -> g_A (plain float), y rows -> g_Bd (duplicated ull).
// ---------------------------------------------------------------------------
__global__ void qk_precompute(const float* __restrict__ x,
                              const float* __restrict__ y,
                              int n, int m, int d) {
    int tid = blockIdx.x * blockDim.x + threadIdx.x;
    int total = (n + m) * 8;
    if (tid >= total) return;
    int g = tid & 7;
    int r = tid >> 3;
    float s0, c0, s1, c1;
    if (r < n) {
        const float* src = x + (size_t)r * d;
        sincosf(0.5f * src[2 * g],     &s0, &c0);
        sincosf(0.5f * src[2 * g + 1], &s1, &c1);
        g_A[(g * 4 + 0) * n + r] = c0 * c1;
        g_A[(g * 4 + 1) * n + r] = c0 * s1;
        g_A[(g * 4 + 2) * n + r] = s0 * c1;
        g_A[(g * 4 + 3) * n + r] = s0 * s1;
    } else {
        r -= n;
        const float* src = y + (size_t)r * d;
        sincosf(0.5f * src[2 * g],     &s0, &c0);
        sincosf(0.5f * src[2 * g + 1], &s1, &c1);
        ull v;
        DUP_TO_ULL(v, c0 * c1); g_Bd[(g * 4 + 0) * m + r] = v;
        DUP_TO_ULL(v, c0 * s1); g_Bd[(g * 4 + 1) * m + r] = v;
        DUP_TO_ULL(v, s0 * c1); g_Bd[(g * 4 + 2) * m + r] = v;
        DUP_TO_ULL(v, s0 * s1); g_Bd[(g * 4 + 3) * m + r] = v;
    }
}

// ---------------------------------------------------------------------------
// Main kernel: CTA tile 64(i) x 64(j), 128 threads, per-thread 8i x 4j with
// f32x2 packed over i. A packed pairs come straight from smem; B is stored
// pre-duplicated, so the inner loop has ZERO mov-duplications:
// per g per thread: 16 x LDS.128 + 80 packed FMA/MUL (83% fma issue mix).
// Sequential-p accumulation keeps live regs ~92 -> 5 CTAs/SM.
// ---------------------------------------------------------------------------
__global__ __launch_bounds__(128, 5)
void qk_prod(float* __restrict__ out, int n, int m) {
    __shared__ float As[32][64];   // [g*4+p][i_local]          8 KB
    __shared__ ull   Bs[32][64];   // [g*4+p][j_local] (dup'd)  16 KB

    const int i_base = blockIdx.y * 64;
    const int j_base = blockIdx.x * 64;
    const int tid = threadIdx.x;

    // Fill As: 512 float4 chunks.
    #pragma unroll
    for (int k = 0; k < 4; k++) {
        int idx = tid + k * 128;
        int slice = idx >> 4;
        int pos = (idx & 15) << 2;
        *(float4*)&As[slice][pos] =
            *(const float4*)&g_A[(size_t)slice * n + i_base + pos];
    }
    // Fill Bs: 1024 ulonglong2 chunks.
    #pragma unroll
    for (int k = 0; k < 8; k++) {
        int idx = tid + k * 128;
        int slice = idx >> 5;
        int pos = (idx & 31) << 1;
        *(ulonglong2*)&Bs[slice][pos] =
            *(const ulonglong2*)&g_Bd[(size_t)slice * m + j_base + pos];
    }
    __syncthreads();

    const int ty = tid & 7;        // i direction: 8 threads x 8 = 64
    const int tx = tid >> 3;       // j direction: 16 threads x 4 = 64
    const int i0 = ty * 8;
    const int j0 = tx * 4;

    ull prod[4][4];                // [ipair][jj]

    #pragma unroll 1
    for (int g = 0; g < 8; g++) {
        ull t[4][4];
        #pragma unroll
        for (int p = 0; p < 4; p++) {
            // A: 8 consecutive i-values = 4 packed pairs (2 x LDS.128).
            ulonglong2 a01 = *(const ulonglong2*)&As[g * 4 + p][i0];
            ulonglong2 a23 = *(const ulonglong2*)&As[g * 4 + p][i0 + 4];
            ull a[4] = {a01.x, a01.y, a23.x, a23.y};
            // B: 4 pre-duplicated values (2 x LDS.128).
            ulonglong2 b01 = *(const ulonglong2*)&Bs[g * 4 + p][j0];
            ulonglong2 b23 = *(const ulonglong2*)&Bs[g * 4 + p][j0 + 2];
            ull b[4] = {b01.x, b01.y, b23.x, b23.y};
            if (p == 0) {
                #pragma unroll
                for (int ii = 0; ii < 4; ii++)
                    #pragma unroll
                    for (int jj = 0; jj < 4; jj++)
                        MUL_F32X2(t[ii][jj], a[ii], b[jj]);
            } else {
                #pragma unroll
                for (int ii = 0; ii < 4; ii++)
                    #pragma unroll
                    for (int jj = 0; jj < 4; jj++)
                        FMA_F32X2(t[ii][jj], a[ii], b[jj]);
            }
        }
        if (g == 0) {
            #pragma unroll
            for (int ii = 0; ii < 4; ii++)
                #pragma unroll
                for (int jj = 0; jj < 4; jj++)
                    prod[ii][jj] = t[ii][jj];
        } else {
            #pragma unroll
            for (int ii = 0; ii < 4; ii++)
                #pragma unroll
                for (int jj = 0; jj < 4; jj++)
                    MUL_F32X2(prod[ii][jj], prod[ii][jj], t[ii][jj]);
        }
    }

    // Epilogue: abs, unpack i-pairs, store one float4 per row.
    #pragma unroll
    for (int ii = 0; ii < 4; ii++) {
        float lo0, hi0, lo1, hi1, lo2, hi2, lo3, hi3;
        ull v;
        ABS_F32X2(v, prod[ii][0]); UNPACK_F32X2(lo0, hi0, v);
        ABS_F32X2(v, prod[ii][1]); UNPACK_F32X2(lo1, hi1, v);
        ABS_F32X2(v, prod[ii][2]); UNPACK_F32X2(lo2, hi2, v);
        ABS_F32X2(v, prod[ii][3]); UNPACK_F32X2(lo3, hi3, v);
        int row0 = i_base + i0 + 2 * ii;
        *(float4*)&out[(size_t)row0 * m + j_base + j0] =
            make_float4(lo0, lo1, lo2, lo3);
        *(float4*)&out[(size_t)(row0 + 1) * m + j_base + j0] =
            make_float4(hi0, hi1, hi2, hi3);
    }
}

// ---------------------------------------------------------------------------
// Generic fallback (shape-robust, slow): one thread per output.
// ---------------------------------------------------------------------------
__global__ void qk_generic(const float* __restrict__ x, const float* __restrict__ y,
                           float* __restrict__ out, int n, int m, int d) {
    long long idx = (long long)blockIdx.x * blockDim.x + threadIdx.x;
    long long total = (long long)n * m;
    if (idx >= total) return;
    int i = (int)(idx / m);
    int j = (int)(idx % m);
    float prod = 1.0f;
    for (int k = 0; k < d; k++)
        prod *= cosf(0.5f * (x[(size_t)i * d + k] - y[(size_t)j * d + k]));
    out[idx] = fabsf(prod);
}

extern "C" void kernel_launch(void* const* d_in, const int* in_sizes, int n_in,
                              void* d_out, int out_size) {
    const float* x = (const float*)d_in[0];
    const float* y = (const float*)d_in[1];
    float* out = (float*)d_out;

    double dd = sqrt((double)in_sizes[0] * (double)in_sizes[1] / (double)out_size);
    int d = (int)(dd + 0.5);
    if (d <= 0) d = 16;
    int n = in_sizes[0] / d;
    int m = in_sizes[1] / d;

    bool fast = (d == 16) && (n % 64 == 0) && (m % 64 == 0) &&
                (n <= MAXROWS) && (m <= MAXROWS) &&
                ((long long)n * d == in_sizes[0]) &&
                ((long long)m * d == in_sizes[1]) &&
                ((long long)n * m == out_size);

    if (fast) {
        int total = (n + m) * 8;
        qk_precompute<<<(total + 255) / 256, 256>>>(x, y, n, m, d);
        dim3 grid(m / 64, n / 64);
        qk_prod<<<grid, 128>>>(out, n, m);
    } else {
        long long total = (long long)n * m;
        int blocks = (int)((total + 255) / 256);
        qk_generic<<<blocks, 256>>>(x, y, out, n, m, d);
    }
}